// round 9
// baseline (speedup 1.0000x reference)
#include <cuda_runtime.h>
#include <cuda_bf16.h>
#include <cuda_fp16.h>
#include <cstdint>

#define NN 50000
#define NE 800000
#define DIM 128
#define NG 64
#define SCAN_B 256
#define NBLK ((NN + SCAN_B - 1) / SCAN_B)   // 196

// ---------------- static device scratch -------------------------------------
static __device__ float    g_hA [NN * DIM];       // fp32 layer outputs (ping)
static __device__ float    g_hB [NN * DIM];       // fp32 layer outputs (pong)
static __device__ uint16_t g_xh[NN * DIM];        // bf16 hi of x
static __device__ uint16_t g_xl[NN * DIM];
static __device__ uint16_t g_hh0[NN * DIM];       // bf16 hi of h0
static __device__ uint16_t g_hl0[NN * DIM];
static __device__ uint16_t g_hh1[NN * DIM];       // bf16 hi of h1
static __device__ uint16_t g_hl1[NN * DIM];
static __device__ uint16_t g_xf16[NN * DIM];      // fp16 copy of x  (agg gather)
static __device__ uint16_t g_hf0 [NN * DIM];      // fp16 copy of h0 (agg gather)
static __device__ uint16_t g_hf1 [NN * DIM];      // fp16 copy of h1 (agg gather)
static __device__ uint16_t g_Wbh[6 * 16384];      // bf16 hi of Wl0,Wr0,Wl1,Wr1,Wl2,Wr2
static __device__ uint16_t g_Wbl[6 * 16384];
static __device__ int   g_deg[NN];
static __device__ int   g_rowstart[NN];
static __device__ int   g_cursor[NN];
static __device__ float g_invdeg[NN];
static __device__ int   g_csr[NE];
static __device__ int   g_gcnt[NG];
static __device__ int   g_bsum[NBLK];
static __device__ int   g_boff[NBLK];

// ---------------- helpers ----------------------------------------------------
__device__ __forceinline__ uint32_t smem_u32(const void* p) {
    uint32_t a;
    asm("{ .reg .u64 t; cvta.to.shared.u64 t, %1; cvt.u32.u64 %0, t; }"
        : "=r"(a) : "l"(p));
    return a;
}

__device__ __forceinline__ void bf16_split(float v, uint16_t& h, uint16_t& l) {
    __nv_bfloat16 hb = __float2bfloat16(v);
    float hf = __bfloat162float(hb);
    __nv_bfloat16 lb = __float2bfloat16(v - hf);
    h = __bfloat16_as_ushort(hb);
    l = __bfloat16_as_ushort(lb);
}

#define LDSM_X4(r, addr) \
    asm volatile("ldmatrix.sync.aligned.m8n8.x4.shared.b16 {%0,%1,%2,%3}, [%4];" \
        : "=r"((r)[0]), "=r"((r)[1]), "=r"((r)[2]), "=r"((r)[3]) : "r"(addr))

#define MMA_BF16(d, a, b0v, b1v) \
    asm volatile("mma.sync.aligned.m16n8k16.row.col.f32.bf16.bf16.f32 " \
        "{%0,%1,%2,%3}, {%4,%5,%6,%7}, {%8,%9}, {%0,%1,%2,%3};" \
        : "+f"((d)[0]), "+f"((d)[1]), "+f"((d)[2]), "+f"((d)[3]) \
        : "r"((a)[0]), "r"((a)[1]), "r"((a)[2]), "r"((a)[3]), \
          "r"(b0v), "r"(b1v))

// ---------------- init --------------------------------------------------------
__global__ void k_zero() {
    int i = blockIdx.x * blockDim.x + threadIdx.x;
    if (i < NN) g_deg[i] = 0;
    if (i < NG) g_gcnt[i] = 0;
}

// cvtX + degree count + graph count fused (one big grid)
__global__ void k_prep(const float* __restrict__ x, const int* __restrict__ ei,
                       const int* __restrict__ batch) {
    int i = blockIdx.x * blockDim.x + threadIdx.x;
    if (i < NN * DIM) {
        float v = x[i];
        uint16_t h, l;
        bf16_split(v, h, l);
        g_xh[i] = h; g_xl[i] = l;
        g_xf16[i] = __half_as_ushort(__float2half_rn(v));
    }
    if (i < NE) atomicAdd(&g_deg[ei[NE + i]], 1);
    if (i < NN) atomicAdd(&g_gcnt[batch[i]], 1);
}

// all six weight matrices in one kernel
__global__ void k_cvtW_all(const float* __restrict__ w0, const float* __restrict__ w1,
                           const float* __restrict__ w2, const float* __restrict__ w3,
                           const float* __restrict__ w4, const float* __restrict__ w5) {
    int i = blockIdx.x * blockDim.x + threadIdx.x;
    if (i >= 6 * 16384) return;
    int sel = i >> 14;
    int off = i & 16383;
    const float* w = (sel == 0) ? w0 : (sel == 1) ? w1 : (sel == 2) ? w2
                   : (sel == 3) ? w3 : (sel == 4) ? w4 : w5;
    uint16_t h, l;
    bf16_split(w[off], h, l);
    g_Wbh[i] = h; g_Wbl[i] = l;
}

// ---------------- hierarchical scan of degrees ------------------------------
__global__ void k_blocksum() {
    __shared__ int wsum[8];
    int i = blockIdx.x * SCAN_B + threadIdx.x;
    int v = (i < NN) ? g_deg[i] : 0;
    int s = v;
#pragma unroll
    for (int o = 16; o > 0; o >>= 1) s += __shfl_down_sync(0xffffffffu, s, o);
    if ((threadIdx.x & 31) == 0) wsum[threadIdx.x >> 5] = s;
    __syncthreads();
    if (threadIdx.x == 0) {
        int t = 0;
#pragma unroll
        for (int w = 0; w < 8; w++) t += wsum[w];
        g_bsum[blockIdx.x] = t;
    }
}

__global__ void k_scan2() {
    __shared__ int sh[SCAN_B];
    int t = threadIdx.x;
    sh[t] = (t < NBLK) ? g_bsum[t] : 0;
    __syncthreads();
#pragma unroll
    for (int off = 1; off < SCAN_B; off <<= 1) {
        int v = (t >= off) ? sh[t - off] : 0;
        __syncthreads();
        sh[t] += v;
        __syncthreads();
    }
    if (t < NBLK) g_boff[t] = (t > 0) ? sh[t - 1] : 0;
}

__global__ void k_apply() {
    __shared__ int wsum[8];
    int lane = threadIdx.x & 31;
    int wid  = threadIdx.x >> 5;
    int i = blockIdx.x * SCAN_B + threadIdx.x;
    int v = (i < NN) ? g_deg[i] : 0;
    int inc = v;
#pragma unroll
    for (int o = 1; o < 32; o <<= 1) {
        int u = __shfl_up_sync(0xffffffffu, inc, o);
        if (lane >= o) inc += u;
    }
    if (lane == 31) wsum[wid] = inc;
    __syncthreads();
    if (wid == 0) {
        int ws = (lane < 8) ? wsum[lane] : 0;
#pragma unroll
        for (int o = 1; o < 8; o <<= 1) {
            int u = __shfl_up_sync(0xffffffffu, ws, o);
            if (lane >= o) ws += u;
        }
        if (lane < 8) wsum[lane] = ws;
    }
    __syncthreads();
    int excl = inc - v + ((wid > 0) ? wsum[wid - 1] : 0) + g_boff[blockIdx.x];
    if (i < NN) {
        g_rowstart[i] = excl;
        g_cursor[i]   = excl;
        g_invdeg[i]   = (v > 0) ? 1.0f / (float)v : 0.0f;
    }
}

__global__ void k_fill(const int* __restrict__ ei) {
    int e = blockIdx.x * blockDim.x + threadIdx.x;
    if (e >= NE) return;
    int s = ei[e];
    int d = ei[NE + e];
    int pos = atomicAdd(&g_cursor[d], 1);
    g_csr[pos] = s;
}

// ---------------- fused layer: agg (smem) + bf16-split tensor GEMM ----------
// Phase A: warp-per-node fp16 gather -> mean -> bf16 hi/lo in smem A-tile.
// Phase B: mma.sync GEMM; chunks 0-3 A from smem agg tile, 4-7 from rs global.
#define AST  40    // staging tile row stride (80B rows, conflict-free ldmatrix)
#define AGT  136   // agg tile row stride (272B rows, conflict-free ldmatrix)
#define LAYER_DSMEM 110592

__global__ void __launch_bounds__(256, 2) k_layer(
    int layer, const float* __restrict__ bl)
{
    extern __shared__ uint16_t dsm[];
    uint16_t* sAggH = dsm;                 // 128*136 = 17408 elems
    uint16_t* sAggL = dsm + 17408;
    uint16_t* sAh   = dsm + 34816;         // 128*40 = 5120 elems
    uint16_t* sAl   = dsm + 39936;
    uint16_t* sBh   = dsm + 45056;
    uint16_t* sBl   = dsm + 50176;         // ends at 55296 elems = 110592 B
    __shared__ float bias_s[128];

    const uint16_t* gatherf;
    const uint16_t* rsh;
    const uint16_t* rsl;
    float*    hout;
    uint16_t* outh;
    uint16_t* outl;
    uint16_t* outf;
    int woff, relu, emit;
    if (layer == 0) {
        gatherf = g_xf16; rsh = g_xh;  rsl = g_xl;  woff = 0;
        hout = g_hA; outh = g_hh0; outl = g_hl0; outf = g_hf0; relu = 1; emit = 1;
    } else if (layer == 1) {
        gatherf = g_hf0;  rsh = g_hh0; rsl = g_hl0; woff = 32768;
        hout = g_hB; outh = g_hh1; outl = g_hl1; outf = g_hf1; relu = 1; emit = 1;
    } else {
        gatherf = g_hf1;  rsh = g_hh1; rsl = g_hl1; woff = 65536;
        hout = g_hA; outh = nullptr; outl = nullptr; outf = nullptr; relu = 0; emit = 0;
    }

    int tid  = threadIdx.x;
    int wid  = tid >> 5;
    int lane = tid & 31;
    int nb   = blockIdx.x * 128;
    int m0   = (wid & 3) * 32;
    int n0   = (wid >> 2) * 64;

    if (tid < 128) bias_s[tid] = bl[tid];

    // ======== Phase A: aggregate 16 nodes per warp into smem tile ========
    const uint2* x2 = (const uint2*)gatherf;    // 4 fp16 per lane
    for (int t = 0; t < 16; t++) {
        int row  = (wid << 4) + t;
        int node = nb + row;
        float a0 = 0.f, a1 = 0.f, a2 = 0.f, a3 = 0.f;
        if (node < NN) {
            int start = g_rowstart[node];
            int d     = g_deg[node];
            float inv = g_invdeg[node];
            int j = 0;
            for (; j + 8 <= d; j += 8) {
                int si[8];
#pragma unroll
                for (int u = 0; u < 8; u++) si[u] = g_csr[start + j + u];
                uint2 uu[8];
#pragma unroll
                for (int u = 0; u < 8; u++) uu[u] = x2[si[u] * 32 + lane];
#pragma unroll
                for (int u = 0; u < 8; u++) {
                    float2 pa = __half22float2(*(__half2*)&uu[u].x);
                    float2 pb = __half22float2(*(__half2*)&uu[u].y);
                    a0 += pa.x; a1 += pa.y; a2 += pb.x; a3 += pb.y;
                }
            }
            for (; j + 4 <= d; j += 4) {
                int si[4];
#pragma unroll
                for (int u = 0; u < 4; u++) si[u] = g_csr[start + j + u];
#pragma unroll
                for (int u = 0; u < 4; u++) {
                    uint2 uu = x2[si[u] * 32 + lane];
                    float2 pa = __half22float2(*(__half2*)&uu.x);
                    float2 pb = __half22float2(*(__half2*)&uu.y);
                    a0 += pa.x; a1 += pa.y; a2 += pb.x; a3 += pb.y;
                }
            }
            for (; j < d; j++) {
                int s0 = g_csr[start + j];
                uint2 uu = x2[s0 * 32 + lane];
                float2 pa = __half22float2(*(__half2*)&uu.x);
                float2 pb = __half22float2(*(__half2*)&uu.y);
                a0 += pa.x; a1 += pa.y; a2 += pb.x; a3 += pb.y;
            }
            a0 *= inv; a1 *= inv; a2 *= inv; a3 *= inv;
        }
        uint16_t h0, l0, h1, l1, h2, l2, h3, l3;
        bf16_split(a0, h0, l0); bf16_split(a1, h1, l1);
        bf16_split(a2, h2, l2); bf16_split(a3, h3, l3);
        *(uint2*)&sAggH[row * AGT + lane * 4] =
            make_uint2((uint32_t)h0 | ((uint32_t)h1 << 16),
                       (uint32_t)h2 | ((uint32_t)h3 << 16));
        *(uint2*)&sAggL[row * AGT + lane * 4] =
            make_uint2((uint32_t)l0 | ((uint32_t)l1 << 16),
                       (uint32_t)l2 | ((uint32_t)l3 << 16));
    }
    __syncthreads();

    // ======== Phase B: GEMM ========
    float acc[2][8][4];
#pragma unroll
    for (int i = 0; i < 2; i++)
#pragma unroll
        for (int j = 0; j < 8; j++)
#pragma unroll
            for (int q = 0; q < 4; q++) acc[i][j][q] = 0.f;

    for (int chunk = 0; chunk < 8; chunk++) {
        int kk0 = (chunk & 3) * 32;
        const uint16_t* pBh = g_Wbh + woff + ((chunk < 4) ? 0 : 16384);
        const uint16_t* pBl = g_Wbl + woff + ((chunk < 4) ? 0 : 16384);

        __syncthreads();
        if (chunk >= 4) {
#pragma unroll
            for (int r = 0; r < 2; r++) {
                int c   = tid + r * 256;
                int row = c >> 2;
                int seg = c & 3;
                int node = nb + row;
                uint4 vh = make_uint4(0, 0, 0, 0), vl = make_uint4(0, 0, 0, 0);
                if (node < NN) {
                    vh = *(const uint4*)&rsh[node * 128 + kk0 + seg * 8];
                    vl = *(const uint4*)&rsl[node * 128 + kk0 + seg * 8];
                }
                *(uint4*)&sAh[row * AST + seg * 8] = vh;
                *(uint4*)&sAl[row * AST + seg * 8] = vl;
            }
        }
#pragma unroll
        for (int r = 0; r < 2; r++) {
            int c   = tid + r * 256;
            int row = c >> 2;
            int seg = c & 3;
            uint4 wh = *(const uint4*)&pBh[row * 128 + kk0 + seg * 8];
            uint4 wl = *(const uint4*)&pBl[row * 128 + kk0 + seg * 8];
            *(uint4*)&sBh[row * AST + seg * 8] = wh;
            *(uint4*)&sBl[row * AST + seg * 8] = wl;
        }
        __syncthreads();

        bool useAgg = (chunk < 4);
#pragma unroll
        for (int ks = 0; ks < 32; ks += 16) {
            uint32_t ah[2][4], alr[2][4], bh[4][4], blr[4][4];
#pragma unroll
            for (int mt = 0; mt < 2; mt++) {
                int row = m0 + mt * 16 + (lane & 15);
                if (useAgg) {
                    int col = chunk * 32 + ks + (lane >> 4) * 8;
                    LDSM_X4(ah[mt],  smem_u32(&sAggH[row * AGT + col]));
                    LDSM_X4(alr[mt], smem_u32(&sAggL[row * AGT + col]));
                } else {
                    int col = ks + (lane >> 4) * 8;
                    LDSM_X4(ah[mt],  smem_u32(&sAh[row * AST + col]));
                    LDSM_X4(alr[mt], smem_u32(&sAl[row * AST + col]));
                }
            }
#pragma unroll
            for (int bt = 0; bt < 4; bt++) {
                int row = n0 + bt * 16 + (lane & 7) + ((lane >> 4) & 1) * 8;
                int col = ks + ((lane >> 3) & 1) * 8;
                LDSM_X4(bh[bt],  smem_u32(&sBh[row * AST + col]));
                LDSM_X4(blr[bt], smem_u32(&sBl[row * AST + col]));
            }
#pragma unroll
            for (int mt = 0; mt < 2; mt++)
#pragma unroll
                for (int nt = 0; nt < 8; nt++) {
                    int bg = nt >> 1, pr = (nt & 1) * 2;
                    MMA_BF16(acc[mt][nt], ah[mt],  bh[bg][pr],  bh[bg][pr + 1]);
                    MMA_BF16(acc[mt][nt], alr[mt], bh[bg][pr],  bh[bg][pr + 1]);
                    MMA_BF16(acc[mt][nt], ah[mt],  blr[bg][pr], blr[bg][pr + 1]);
                }
        }
    }

    // ---- epilogue ----
    int g  = lane >> 2;
    int tg = lane & 3;
#pragma unroll
    for (int mt = 0; mt < 2; mt++)
#pragma unroll
        for (int nt = 0; nt < 8; nt++) {
            int colb = n0 + nt * 8 + tg * 2;
            float b0 = bias_s[colb], b1 = bias_s[colb + 1];
#pragma unroll
            for (int half = 0; half < 2; half++) {
                int row = nb + m0 + mt * 16 + g + half * 8;
                if (row >= NN) continue;
                float v0 = acc[mt][nt][half * 2 + 0] + b0;
                float v1 = acc[mt][nt][half * 2 + 1] + b1;
                if (relu) { v0 = fmaxf(v0, 0.f); v1 = fmaxf(v1, 0.f); }
                *(float2*)&hout[row * 128 + colb] = make_float2(v0, v1);
                if (emit) {
                    uint16_t h0, l0, h1, l1;
                    bf16_split(v0, h0, l0);
                    bf16_split(v1, h1, l1);
                    *(uint32_t*)&outh[row * 128 + colb] =
                        (uint32_t)h0 | ((uint32_t)h1 << 16);
                    *(uint32_t*)&outl[row * 128 + colb] =
                        (uint32_t)l0 | ((uint32_t)l1 << 16);
                    __half2 f2 = __floats2half2_rn(v0, v1);
                    *(uint32_t*)&outf[row * 128 + colb] = *(uint32_t*)&f2;
                }
            }
        }
}

// ---------------- global mean pool ------------------------------------------
__global__ void k_pool(float* __restrict__ out) {
    int g = blockIdx.x;
    int c = threadIdx.x;
    int start = 0;
    for (int i = 0; i < g; i++) start += g_gcnt[i];
    int cnt = g_gcnt[g];
    float s = 0.f;
    for (int r = 0; r < cnt; r++)
        s += g_hA[(start + r) * 128 + c];
    out[g * 128 + c] = (cnt > 0) ? s / (float)cnt : 0.0f;
}

// ---------------- launch ----------------------------------------------------
extern "C" void kernel_launch(void* const* d_in, const int* in_sizes, int n_in,
                              void* d_out, int out_size)
{
    const float* x     = (const float*)d_in[0];
    const int*   ei    = (const int*)d_in[1];
    const int*   batch = (const int*)d_in[2];
    const float* Wl0 = (const float*)d_in[3];
    const float* bl0 = (const float*)d_in[4];
    const float* Wr0 = (const float*)d_in[5];
    const float* Wl1 = (const float*)d_in[6];
    const float* bl1 = (const float*)d_in[7];
    const float* Wr1 = (const float*)d_in[8];
    const float* Wl2 = (const float*)d_in[9];
    const float* bl2 = (const float*)d_in[10];
    const float* Wr2 = (const float*)d_in[11];
    float* out = (float*)d_out;

    (void)cudaFuncSetAttribute(k_layer,
                               cudaFuncAttributeMaxDynamicSharedMemorySize,
                               LAYER_DSMEM);

    k_zero<<<(NN + 255) / 256, 256>>>();
    k_prep<<<(NN * DIM + 255) / 256, 256>>>(x, ei, batch);
    k_blocksum<<<NBLK, SCAN_B>>>();
    k_scan2<<<1, SCAN_B>>>();
    k_apply<<<NBLK, SCAN_B>>>();
    k_fill<<<(NE + 255) / 256, 256>>>(ei);
    k_cvtW_all<<<(6 * 16384 + 255) / 256, 256>>>(Wl0, Wr0, Wl1, Wr1, Wl2, Wr2);

    int blocks = (NN + 127) / 128;   // 391
    k_layer<<<blocks, 256, LAYER_DSMEM>>>(0, bl0);
    k_layer<<<blocks, 256, LAYER_DSMEM>>>(1, bl1);
    k_layer<<<blocks, 256, LAYER_DSMEM>>>(2, bl2);
    k_pool<<<NG, 128>>>(out);
}

// round 10
// speedup vs baseline: 1.3512x; 1.3512x over previous
#include <cuda_runtime.h>
#include <cuda_bf16.h>
#include <cstdint>

#define NN 50000
#define NE 800000
#define DIM 128
#define NG 64
#define SCAN_B 256
#define NBLK ((NN + SCAN_B - 1) / SCAN_B)   // 196

// ---------------- static device scratch -------------------------------------
static __device__ float    g_hA [NN * DIM];       // fp32 layer outputs (ping)
static __device__ float    g_hB [NN * DIM];       // fp32 layer outputs (pong)
static __device__ uint16_t g_aggh[NN * DIM];      // bf16 hi of mean-agg
static __device__ uint16_t g_aggl[NN * DIM];      // bf16 lo
static __device__ uint16_t g_xh[NN * DIM];        // bf16 hi of x
static __device__ uint16_t g_xl[NN * DIM];
static __device__ uint16_t g_hh0[NN * DIM];       // bf16 hi of h0
static __device__ uint16_t g_hl0[NN * DIM];
static __device__ uint16_t g_hh1[NN * DIM];       // bf16 hi of h1
static __device__ uint16_t g_hl1[NN * DIM];
static __device__ uint16_t g_Wbh[6 * 16384];      // bf16 hi of Wl0,Wr0,Wl1,Wr1,Wl2,Wr2
static __device__ uint16_t g_Wbl[6 * 16384];
static __device__ int   g_deg[NN];
static __device__ int   g_rowstart[NN];
static __device__ int   g_cursor[NN];
static __device__ float g_invdeg[NN];
static __device__ int   g_csr[NE];
static __device__ int   g_gcnt[NG];
static __device__ int   g_bsum[NBLK];
static __device__ int   g_boff[NBLK];

// ---------------- helpers ----------------------------------------------------
__device__ __forceinline__ uint32_t smem_u32(const void* p) {
    uint32_t a;
    asm("{ .reg .u64 t; cvta.to.shared.u64 t, %1; cvt.u32.u64 %0, t; }"
        : "=r"(a) : "l"(p));
    return a;
}

__device__ __forceinline__ void bf16_split(float v, uint16_t& h, uint16_t& l) {
    __nv_bfloat16 hb = __float2bfloat16(v);
    float hf = __bfloat162float(hb);
    __nv_bfloat16 lb = __float2bfloat16(v - hf);
    h = __bfloat16_as_ushort(hb);
    l = __bfloat16_as_ushort(lb);
}

#define LDSM_X4(r, addr) \
    asm volatile("ldmatrix.sync.aligned.m8n8.x4.shared.b16 {%0,%1,%2,%3}, [%4];" \
        : "=r"((r)[0]), "=r"((r)[1]), "=r"((r)[2]), "=r"((r)[3]) : "r"(addr))

#define MMA_BF16(d, a, b0v, b1v) \
    asm volatile("mma.sync.aligned.m16n8k16.row.col.f32.bf16.bf16.f32 " \
        "{%0,%1,%2,%3}, {%4,%5,%6,%7}, {%8,%9}, {%0,%1,%2,%3};" \
        : "+f"((d)[0]), "+f"((d)[1]), "+f"((d)[2]), "+f"((d)[3]) \
        : "r"((a)[0]), "r"((a)[1]), "r"((a)[2]), "r"((a)[3]), \
          "r"(b0v), "r"(b1v))

// ---------------- init + fused prep ------------------------------------------
__global__ void k_zero() {
    int i = blockIdx.x * blockDim.x + threadIdx.x;
    if (i < NN) g_deg[i] = 0;
    if (i < NG) g_gcnt[i] = 0;
}

// cvtX (bf16 split) + degree count + graph count in one grid
__global__ void k_prep(const float* __restrict__ x, const int* __restrict__ ei,
                       const int* __restrict__ batch) {
    int i = blockIdx.x * blockDim.x + threadIdx.x;
    if (i < NN * DIM) {
        uint16_t h, l;
        bf16_split(x[i], h, l);
        g_xh[i] = h; g_xl[i] = l;
    }
    if (i < NE) atomicAdd(&g_deg[ei[NE + i]], 1);
    if (i < NN) atomicAdd(&g_gcnt[batch[i]], 1);
}

// all six weight matrices in one kernel
__global__ void k_cvtW_all(const float* __restrict__ w0, const float* __restrict__ w1,
                           const float* __restrict__ w2, const float* __restrict__ w3,
                           const float* __restrict__ w4, const float* __restrict__ w5) {
    int i = blockIdx.x * blockDim.x + threadIdx.x;
    if (i >= 6 * 16384) return;
    int sel = i >> 14;
    int off = i & 16383;
    const float* w = (sel == 0) ? w0 : (sel == 1) ? w1 : (sel == 2) ? w2
                   : (sel == 3) ? w3 : (sel == 4) ? w4 : w5;
    uint16_t h, l;
    bf16_split(w[off], h, l);
    g_Wbh[i] = h; g_Wbl[i] = l;
}

// ---------------- hierarchical scan of degrees ------------------------------
__global__ void k_blocksum() {
    __shared__ int wsum[8];
    int i = blockIdx.x * SCAN_B + threadIdx.x;
    int v = (i < NN) ? g_deg[i] : 0;
    int s = v;
#pragma unroll
    for (int o = 16; o > 0; o >>= 1) s += __shfl_down_sync(0xffffffffu, s, o);
    if ((threadIdx.x & 31) == 0) wsum[threadIdx.x >> 5] = s;
    __syncthreads();
    if (threadIdx.x == 0) {
        int t = 0;
#pragma unroll
        for (int w = 0; w < 8; w++) t += wsum[w];
        g_bsum[blockIdx.x] = t;
    }
}

__global__ void k_scan2() {
    __shared__ int sh[SCAN_B];
    int t = threadIdx.x;
    sh[t] = (t < NBLK) ? g_bsum[t] : 0;
    __syncthreads();
#pragma unroll
    for (int off = 1; off < SCAN_B; off <<= 1) {
        int v = (t >= off) ? sh[t - off] : 0;
        __syncthreads();
        sh[t] += v;
        __syncthreads();
    }
    if (t < NBLK) g_boff[t] = (t > 0) ? sh[t - 1] : 0;
}

__global__ void k_apply() {
    __shared__ int wsum[8];
    int lane = threadIdx.x & 31;
    int wid  = threadIdx.x >> 5;
    int i = blockIdx.x * SCAN_B + threadIdx.x;
    int v = (i < NN) ? g_deg[i] : 0;
    int inc = v;
#pragma unroll
    for (int o = 1; o < 32; o <<= 1) {
        int u = __shfl_up_sync(0xffffffffu, inc, o);
        if (lane >= o) inc += u;
    }
    if (lane == 31) wsum[wid] = inc;
    __syncthreads();
    if (wid == 0) {
        int ws = (lane < 8) ? wsum[lane] : 0;
#pragma unroll
        for (int o = 1; o < 8; o <<= 1) {
            int u = __shfl_up_sync(0xffffffffu, ws, o);
            if (lane >= o) ws += u;
        }
        if (lane < 8) wsum[lane] = ws;
    }
    __syncthreads();
    int excl = inc - v + ((wid > 0) ? wsum[wid - 1] : 0) + g_boff[blockIdx.x];
    if (i < NN) {
        g_rowstart[i] = excl;
        g_cursor[i]   = excl;
        g_invdeg[i]   = (v > 0) ? 1.0f / (float)v : 0.0f;
    }
}

__global__ void k_fill(const int* __restrict__ ei) {
    int e = blockIdx.x * blockDim.x + threadIdx.x;
    if (e >= NE) return;
    int s = ei[e];
    int d = ei[NE + e];
    int pos = atomicAdd(&g_cursor[d], 1);
    g_csr[pos] = s;
}

// ---------------- mean aggregation (warp per node, fp32 gather) -------------
__global__ void k_agg(const float* __restrict__ x, int sel) {
    const float* hin = (sel == 0) ? x : ((sel == 1) ? g_hA : g_hB);
    int gw   = (blockIdx.x * blockDim.x + threadIdx.x) >> 5;
    int lane = threadIdx.x & 31;
    if (gw >= NN) return;
    int start = g_rowstart[gw];
    int d     = g_deg[gw];
    const float4* x4 = (const float4*)hin;
    float a0 = 0.f, a1 = 0.f, a2 = 0.f, a3 = 0.f;
    int j = 0;
    for (; j + 4 <= d; j += 4) {
        int s0 = g_csr[start + j + 0];
        int s1 = g_csr[start + j + 1];
        int s2 = g_csr[start + j + 2];
        int s3 = g_csr[start + j + 3];
        float4 v0 = x4[s0 * 32 + lane];
        float4 v1 = x4[s1 * 32 + lane];
        float4 v2 = x4[s2 * 32 + lane];
        float4 v3 = x4[s3 * 32 + lane];
        a0 += v0.x + v1.x + v2.x + v3.x;
        a1 += v0.y + v1.y + v2.y + v3.y;
        a2 += v0.z + v1.z + v2.z + v3.z;
        a3 += v0.w + v1.w + v2.w + v3.w;
    }
    for (; j < d; j++) {
        int s0 = g_csr[start + j];
        float4 v = x4[s0 * 32 + lane];
        a0 += v.x; a1 += v.y; a2 += v.z; a3 += v.w;
    }
    float inv = g_invdeg[gw];
    a0 *= inv; a1 *= inv; a2 *= inv; a3 *= inv;
    uint16_t h0, l0, h1, l1, h2, l2, h3, l3;
    bf16_split(a0, h0, l0); bf16_split(a1, h1, l1);
    bf16_split(a2, h2, l2); bf16_split(a3, h3, l3);
    int idx = gw * 128 + lane * 4;
    uint2 ph = make_uint2((uint32_t)h0 | ((uint32_t)h1 << 16),
                          (uint32_t)h2 | ((uint32_t)h3 << 16));
    uint2 pl = make_uint2((uint32_t)l0 | ((uint32_t)l1 << 16),
                          (uint32_t)l2 | ((uint32_t)l3 << 16));
    *(uint2*)&g_aggh[idx] = ph;
    *(uint2*)&g_aggl[idx] = pl;
}

// ---------------- bf16-split tensor GEMM ------------------------------------
#define AST 40   // smem row stride in bf16 elems (80B -> conflict-free ldmatrix)

__global__ void __launch_bounds__(256, 2) k_gemm_mma(
    int layer, const float* __restrict__ bl)
{
    const uint16_t* rsh;
    const uint16_t* rsl;
    float*    hout;
    uint16_t* outh;
    uint16_t* outl;
    int woff, relu, emit;
    if (layer == 0) {
        rsh = g_xh;  rsl = g_xl;  woff = 0;
        hout = g_hA; outh = g_hh0; outl = g_hl0; relu = 1; emit = 1;
    } else if (layer == 1) {
        rsh = g_hh0; rsl = g_hl0; woff = 32768;
        hout = g_hB; outh = g_hh1; outl = g_hl1; relu = 1; emit = 1;
    } else {
        rsh = g_hh1; rsl = g_hl1; woff = 65536;
        hout = g_hA; outh = nullptr; outl = nullptr; relu = 0; emit = 0;
    }

    __shared__ uint16_t sAh[128 * AST];
    __shared__ uint16_t sAl[128 * AST];
    __shared__ uint16_t sBh[128 * AST];
    __shared__ uint16_t sBl[128 * AST];
    __shared__ float bias_s[128];

    int tid  = threadIdx.x;
    int wid  = tid >> 5;
    int lane = tid & 31;
    int nb   = blockIdx.x * 128;
    int m0   = (wid & 3) * 32;
    int n0   = (wid >> 2) * 64;

    if (tid < 128) bias_s[tid] = bl[tid];

    float acc[2][8][4];
#pragma unroll
    for (int i = 0; i < 2; i++)
#pragma unroll
        for (int j = 0; j < 8; j++)
#pragma unroll
            for (int q = 0; q < 4; q++) acc[i][j][q] = 0.f;

    for (int chunk = 0; chunk < 8; chunk++) {
        int kk0 = (chunk & 3) * 32;
        const uint16_t* pAh = (chunk < 4) ? g_aggh : rsh;
        const uint16_t* pAl = (chunk < 4) ? g_aggl : rsl;
        const uint16_t* pBh = g_Wbh + woff + ((chunk < 4) ? 0 : 16384);
        const uint16_t* pBl = g_Wbl + woff + ((chunk < 4) ? 0 : 16384);

        __syncthreads();
#pragma unroll
        for (int r = 0; r < 2; r++) {
            int c   = tid + r * 256;    // 0..511
            int row = c >> 2;
            int seg = c & 3;
            int node = nb + row;
            uint4 vh = make_uint4(0, 0, 0, 0), vl = make_uint4(0, 0, 0, 0);
            if (node < NN) {
                vh = *(const uint4*)&pAh[node * 128 + kk0 + seg * 8];
                vl = *(const uint4*)&pAl[node * 128 + kk0 + seg * 8];
            }
            *(uint4*)&sAh[row * AST + seg * 8] = vh;
            *(uint4*)&sAl[row * AST + seg * 8] = vl;
            uint4 wh = *(const uint4*)&pBh[row * 128 + kk0 + seg * 8];
            uint4 wl = *(const uint4*)&pBl[row * 128 + kk0 + seg * 8];
            *(uint4*)&sBh[row * AST + seg * 8] = wh;
            *(uint4*)&sBl[row * AST + seg * 8] = wl;
        }
        __syncthreads();

#pragma unroll
        for (int ks = 0; ks < 32; ks += 16) {
            uint32_t ah[2][4], alr[2][4], bh[4][4], blr[4][4];
#pragma unroll
            for (int mt = 0; mt < 2; mt++) {
                int row = m0 + mt * 16 + (lane & 15);
                int col = ks + (lane >> 4) * 8;
                LDSM_X4(ah[mt],  smem_u32(&sAh[row * AST + col]));
                LDSM_X4(alr[mt], smem_u32(&sAl[row * AST + col]));
            }
#pragma unroll
            for (int bt = 0; bt < 4; bt++) {
                int row = n0 + bt * 16 + (lane & 7) + ((lane >> 4) & 1) * 8;
                int col = ks + ((lane >> 3) & 1) * 8;
                LDSM_X4(bh[bt],  smem_u32(&sBh[row * AST + col]));
                LDSM_X4(blr[bt], smem_u32(&sBl[row * AST + col]));
            }
#pragma unroll
            for (int mt = 0; mt < 2; mt++)
#pragma unroll
                for (int nt = 0; nt < 8; nt++) {
                    int bg = nt >> 1, pr = (nt & 1) * 2;
                    MMA_BF16(acc[mt][nt], ah[mt],  bh[bg][pr],  bh[bg][pr + 1]);
                    MMA_BF16(acc[mt][nt], alr[mt], bh[bg][pr],  bh[bg][pr + 1]);
                    MMA_BF16(acc[mt][nt], ah[mt],  blr[bg][pr], blr[bg][pr + 1]);
                }
        }
    }

    // ---- epilogue ----
    int g  = lane >> 2;
    int tg = lane & 3;
#pragma unroll
    for (int mt = 0; mt < 2; mt++)
#pragma unroll
        for (int nt = 0; nt < 8; nt++) {
            int colb = n0 + nt * 8 + tg * 2;
            float b0 = bias_s[colb], b1 = bias_s[colb + 1];
#pragma unroll
            for (int half = 0; half < 2; half++) {
                int row = nb + m0 + mt * 16 + g + half * 8;
                if (row >= NN) continue;
                float v0 = acc[mt][nt][half * 2 + 0] + b0;
                float v1 = acc[mt][nt][half * 2 + 1] + b1;
                if (relu) { v0 = fmaxf(v0, 0.f); v1 = fmaxf(v1, 0.f); }
                *(float2*)&hout[row * 128 + colb] = make_float2(v0, v1);
                if (emit) {
                    uint16_t h0, l0, h1, l1;
                    bf16_split(v0, h0, l0);
                    bf16_split(v1, h1, l1);
                    *(uint32_t*)&outh[row * 128 + colb] =
                        (uint32_t)h0 | ((uint32_t)h1 << 16);
                    *(uint32_t*)&outl[row * 128 + colb] =
                        (uint32_t)l0 | ((uint32_t)l1 << 16);
                }
            }
        }
}

// ---------------- global mean pool ------------------------------------------
__global__ void k_pool(float* __restrict__ out) {
    int g = blockIdx.x;
    int c = threadIdx.x;
    int start = 0;
    for (int i = 0; i < g; i++) start += g_gcnt[i];
    int cnt = g_gcnt[g];
    float s = 0.f;
    for (int r = 0; r < cnt; r++)
        s += g_hA[(start + r) * 128 + c];
    out[g * 128 + c] = (cnt > 0) ? s / (float)cnt : 0.0f;
}

// ---------------- launch ----------------------------------------------------
extern "C" void kernel_launch(void* const* d_in, const int* in_sizes, int n_in,
                              void* d_out, int out_size)
{
    const float* x     = (const float*)d_in[0];
    const int*   ei    = (const int*)d_in[1];
    const int*   batch = (const int*)d_in[2];
    const float* Wl0 = (const float*)d_in[3];
    const float* bl0 = (const float*)d_in[4];
    const float* Wr0 = (const float*)d_in[5];
    const float* Wl1 = (const float*)d_in[6];
    const float* bl1 = (const float*)d_in[7];
    const float* Wr1 = (const float*)d_in[8];
    const float* Wl2 = (const float*)d_in[9];
    const float* bl2 = (const float*)d_in[10];
    const float* Wr2 = (const float*)d_in[11];
    float* out = (float*)d_out;

    k_zero<<<(NN + 255) / 256, 256>>>();
    k_prep<<<(NN * DIM + 255) / 256, 256>>>(x, ei, batch);
    k_blocksum<<<NBLK, SCAN_B>>>();
    k_scan2<<<1, SCAN_B>>>();
    k_apply<<<NBLK, SCAN_B>>>();
    k_fill<<<(NE + 255) / 256, 256>>>(ei);
    k_cvtW_all<<<(6 * 16384 + 255) / 256, 256>>>(Wl0, Wr0, Wl1, Wr1, Wl2, Wr2);

    int agg_blocks  = (NN * 32 + 255) / 256;
    int gemm_blocks = (NN + 127) / 128;   // 391

    // layer 0
    k_agg<<<agg_blocks, 256>>>(x, 0);
    k_gemm_mma<<<gemm_blocks, 256>>>(0, bl0);
    // layer 1
    k_agg<<<agg_blocks, 256>>>(x, 1);
    k_gemm_mma<<<gemm_blocks, 256>>>(1, bl1);
    // layer 2
    k_agg<<<agg_blocks, 256>>>(x, 2);
    k_gemm_mma<<<gemm_blocks, 256>>>(2, bl2);
    // pool
    k_pool<<<NG, 128>>>(out);
}